// round 13
// baseline (speedup 1.0000x reference)
#include <cuda_runtime.h>
#include <cuda_bf16.h>
#include <mma.h>

using namespace nvcuda;

#define BB 2048
#define NN 128
#define DD 512

typedef unsigned long long u64;

// static scratch (no allocs allowed)
__device__ float g_cw[2 * BB * DD];                    // 8 MB
__device__ __nv_bfloat16 g_Ah[2 * BB * DD];            // 4 MB  [text;img] hi
__device__ __nv_bfloat16 g_Al[2 * BB * DD];            // 4 MB  lo
__device__ __nv_bfloat16 g_Bh[DD * DD];                // 512 KB cow hi
__device__ __nv_bfloat16 g_Bl[DD * DD];                // 512 KB cow lo

__device__ __forceinline__ float tanh_ap(float x) {
    float y;
    asm("tanh.approx.f32 %0, %1;" : "=f"(y) : "f"(x));
    return y;
}
__device__ __forceinline__ u64 ffma2(u64 a, u64 b, u64 c) {
    u64 d;
    asm("fma.rn.f32x2 %0, %1, %2, %3;" : "=l"(d) : "l"(a), "l"(b), "l"(c));
    return d;
}
__device__ __forceinline__ u64 pack2(float lo, float hi) {
    u64 r;
    asm("mov.b64 %0, {%1, %2};" : "=l"(r) : "f"(lo), "f"(hi));
    return r;
}
__device__ __forceinline__ void unpack2(u64 v, float& lo, float& hi) {
    asm("mov.b64 {%0, %1}, %2;" : "=f"(lo), "=f"(hi) : "l"(v));
}
__device__ __forceinline__ void bsplit(float x, __nv_bfloat16& h, __nv_bfloat16& l) {
    __nv_bfloat16 hh = __float2bfloat16(x);
    h = hh;
    l = __float2bfloat16(x - __bfloat162float(hh));
}
__device__ __forceinline__ void cpa_wait(int pend) {
    if (pend <= 0) asm volatile("cp.async.wait_group 0;" ::: "memory");
    else           asm volatile("cp.async.wait_group 1;" ::: "memory");
}

// ---------------------------------------------------------------------------
// Kernel 0: one-shot fp32 -> bf16 hi/lo split of A=[text;img] and B=cow.
// ---------------------------------------------------------------------------
__global__ __launch_bounds__(256) void convert_inputs(
    const float* __restrict__ text, const float* __restrict__ img,
    const float* __restrict__ cow)
{
    const int bid = blockIdx.x;
    __nv_bfloat16 h[4], l[4];
    if (bid < 2048) {
        const int e = (bid * 256 + threadIdx.x) * 4;
        const int r = e >> 9, c = e & 511;
        const float* src = (r < BB) ? (text + (size_t)r * DD + c)
                                    : (img + (size_t)(r - BB) * DD + c);
        float4 v = *(const float4*)src;
        bsplit(v.x, h[0], l[0]); bsplit(v.y, h[1], l[1]);
        bsplit(v.z, h[2], l[2]); bsplit(v.w, h[3], l[3]);
        uint2 uh, ul;
        uh.x = (unsigned)__bfloat16_as_ushort(h[0]) | ((unsigned)__bfloat16_as_ushort(h[1]) << 16);
        uh.y = (unsigned)__bfloat16_as_ushort(h[2]) | ((unsigned)__bfloat16_as_ushort(h[3]) << 16);
        ul.x = (unsigned)__bfloat16_as_ushort(l[0]) | ((unsigned)__bfloat16_as_ushort(l[1]) << 16);
        ul.y = (unsigned)__bfloat16_as_ushort(l[2]) | ((unsigned)__bfloat16_as_ushort(l[3]) << 16);
        *(uint2*)&g_Ah[e] = uh;
        *(uint2*)&g_Al[e] = ul;
    } else {
        const int e = ((bid - 2048) * 256 + threadIdx.x) * 4;
        float4 v = *(const float4*)(cow + e);
        bsplit(v.x, h[0], l[0]); bsplit(v.y, h[1], l[1]);
        bsplit(v.z, h[2], l[2]); bsplit(v.w, h[3], l[3]);
        uint2 uh, ul;
        uh.x = (unsigned)__bfloat16_as_ushort(h[0]) | ((unsigned)__bfloat16_as_ushort(h[1]) << 16);
        uh.y = (unsigned)__bfloat16_as_ushort(h[2]) | ((unsigned)__bfloat16_as_ushort(h[3]) << 16);
        ul.x = (unsigned)__bfloat16_as_ushort(l[0]) | ((unsigned)__bfloat16_as_ushort(l[1]) << 16);
        ul.y = (unsigned)__bfloat16_as_ushort(l[2]) | ((unsigned)__bfloat16_as_ushort(l[3]) << 16);
        *(uint2*)&g_Bh[e] = uh;
        *(uint2*)&g_Bl[e] = ul;
    }
}

// ---------------------------------------------------------------------------
// Kernel A: cw = A @ cow from preconverted bf16 hi/lo (3 MMA split).
// 128x128 tile, K-chunk 32, 256 threads. grid = (4, 32).
// ---------------------------------------------------------------------------
__global__ __launch_bounds__(256) void cw_gemm()
{
    const int rowBase = blockIdx.y * 128;
    const int colBase = blockIdx.x * 128;
    const int tid = threadIdx.x;
    const int warp = tid >> 5;
    const int wm = warp >> 2;
    const int wn = warp & 3;

    __shared__ __nv_bfloat16 sAh[128][40], sAl[128][40];
    __shared__ __nv_bfloat16 sBh[32][136], sBl[32][136];

    uint4 rAh[2], rAl[2], rBh[2], rBl[2];

    auto gload = [&](int kc) {
#pragma unroll
        for (int it = 0; it < 2; it++) {
            int q = tid + it * 256;
            int r = q >> 2, c8 = (q & 3) * 8;
            rAh[it] = *(const uint4*)&g_Ah[(size_t)(rowBase + r) * DD + kc + c8];
            rAl[it] = *(const uint4*)&g_Al[(size_t)(rowBase + r) * DD + kc + c8];
        }
#pragma unroll
        for (int it = 0; it < 2; it++) {
            int q = tid + it * 256;
            int r = q >> 4, c8 = (q & 15) * 8;
            rBh[it] = *(const uint4*)&g_Bh[(size_t)(kc + r) * DD + colBase + c8];
            rBl[it] = *(const uint4*)&g_Bl[(size_t)(kc + r) * DD + colBase + c8];
        }
    };
    auto sstore = [&]() {
#pragma unroll
        for (int it = 0; it < 2; it++) {
            int q = tid + it * 256;
            int r = q >> 2, c8 = (q & 3) * 8;
            *(uint4*)&sAh[r][c8] = rAh[it];
            *(uint4*)&sAl[r][c8] = rAl[it];
        }
#pragma unroll
        for (int it = 0; it < 2; it++) {
            int q = tid + it * 256;
            int r = q >> 4, c8 = (q & 15) * 8;
            *(uint4*)&sBh[r][c8] = rBh[it];
            *(uint4*)&sBl[r][c8] = rBl[it];
        }
    };

    wmma::fragment<wmma::accumulator, 16, 16, 16, float> acc[4][2];
#pragma unroll
    for (int i = 0; i < 4; i++)
#pragma unroll
        for (int j = 0; j < 2; j++) wmma::fill_fragment(acc[i][j], 0.0f);

    auto compute = [&]() {
#pragma unroll
        for (int ks = 0; ks < 32; ks += 16) {
            wmma::fragment<wmma::matrix_a, 16, 16, 16, __nv_bfloat16, wmma::row_major> ah[4], al[4];
            wmma::fragment<wmma::matrix_b, 16, 16, 16, __nv_bfloat16, wmma::row_major> bh[2], bl[2];
#pragma unroll
            for (int i = 0; i < 4; i++) {
                wmma::load_matrix_sync(ah[i], &sAh[wm*64 + i*16][ks], 40);
                wmma::load_matrix_sync(al[i], &sAl[wm*64 + i*16][ks], 40);
            }
#pragma unroll
            for (int j = 0; j < 2; j++) {
                wmma::load_matrix_sync(bh[j], &sBh[ks][wn*32 + j*16], 136);
                wmma::load_matrix_sync(bl[j], &sBl[ks][wn*32 + j*16], 136);
            }
#pragma unroll
            for (int i = 0; i < 4; i++)
#pragma unroll
                for (int j = 0; j < 2; j++) {
                    wmma::mma_sync(acc[i][j], ah[i], bh[j], acc[i][j]);
                    wmma::mma_sync(acc[i][j], ah[i], bl[j], acc[i][j]);
                    wmma::mma_sync(acc[i][j], al[i], bh[j], acc[i][j]);
                }
        }
    };

    gload(0);
    sstore();
    __syncthreads();
    for (int kc = 32; kc < DD; kc += 32) {
        gload(kc);
        compute();
        __syncthreads();
        sstore();
        __syncthreads();
    }
    compute();

    float* C = g_cw + (size_t)rowBase * DD;
#pragma unroll
    for (int i = 0; i < 4; i++)
#pragma unroll
        for (int j = 0; j < 2; j++)
            wmma::store_matrix_sync(
                C + (size_t)(wm*64 + i*16) * DD + colBase + wn*32 + j*16,
                acc[i][j], DD, wmma::mem_row_major);
}

// ---------------------------------------------------------------------------
// Kernel B: fused co-attention. One CTA/sample, 8 warps (256 thr), 2 CTAs/SM.
// Warp w handles row pairs {16t+2w, 16t+2w+1}; 2-stage x 2-row cp.async ring
// per warp (dynamic smem, 64 KB ring). cw/c0/c1/Wco all read from shared.
// Invalid row b zeroed in regs before any use.
// ---------------------------------------------------------------------------
__global__ __launch_bounds__(256, 2) void fused_coattn(
    const float* __restrict__ text, const float* __restrict__ img,
    const float* __restrict__ comment, const int* __restrict__ comment_num,
    const float* __restrict__ W_ca, const float* __restrict__ W_co,
    float* __restrict__ out)
{
    extern __shared__ float smem[];
    float* s_ring = smem;                    // 8*2*2*512 = 16384 floats (64 KB)
    float* s_c0   = smem + 16384;            // 512
    float* s_c1   = s_c0 + 512;
    float* s_Wca  = s_c1 + 512;
    float* s_Wco  = s_Wca + 512;
    float* s_cw0  = s_Wco + 512;
    float* s_cw1  = s_cw0 + 512;
    float* s_z    = s_cw1 + 512;             // 8
    float* s_scalar = s_z + 8;               // 16

    const int b = blockIdx.x;
    const int tid = threadIdx.x;
    const int lane = tid & 31;
    const int warp = tid >> 5;               // 0..7
    const int M = comment_num[b];
    const float* __restrict__ comment_b = comment + (size_t)b * NN * DD;

    {
        const float* cw0g = g_cw + (size_t)b * DD;
        const float* cw1g = g_cw + (size_t)BB * DD + (size_t)b * DD;
        for (int i = tid; i < DD / 4; i += 256) {
            ((float4*)s_c0)[i]  = ((const float4*)(text + (size_t)b * DD))[i];
            ((float4*)s_c1)[i]  = ((const float4*)(img  + (size_t)b * DD))[i];
            ((float4*)s_Wca)[i] = ((const float4*)W_ca)[i];
            ((float4*)s_Wco)[i] = ((const float4*)W_co)[i];
            ((float4*)s_cw0)[i] = ((const float4*)cw0g)[i];
            ((float4*)s_cw1)[i] = ((const float4*)cw1g)[i];
        }
    }
    __syncthreads();

    u64 acc0p[8], acc1p[8], aap[8];
#pragma unroll
    for (int i = 0; i < 8; i++) { acc0p[i] = 0ull; acc1p[i] = 0ull; aap[i] = 0ull; }
    float Zrun = 0.f;

    // pairs for this warp: rows r0 = 2*warp + 16t, r1 = r0+1 (r1 <= 127 always)
    const int cnt = (M > 2 * warp) ? ((M - 2 * warp + 15) >> 4) : 0;
    const unsigned ring_addr =
        (unsigned)__cvta_generic_to_shared(s_ring + warp * 2048);

    auto issue_pair = [&](int t) {
        const int r0 = 2 * warp + 16 * t;
        const float* g0 = comment_b + (size_t)r0 * DD + lane * 4;
        const unsigned s = ring_addr + ((unsigned)(t & 1) << 12) + ((unsigned)lane << 4);
#pragma unroll
        for (int j = 0; j < 4; j++)
            asm volatile("cp.async.cg.shared.global [%0], [%1], 16;"
                         :: "r"(s + j * 512), "l"(g0 + j * 128) : "memory");
#pragma unroll
        for (int j = 0; j < 4; j++)
            asm volatile("cp.async.cg.shared.global [%0], [%1], 16;"
                         :: "r"(s + 2048 + j * 512), "l"(g0 + DD + j * 128) : "memory");
        asm volatile("cp.async.commit_group;" ::: "memory");
    };

    if (cnt > 0) issue_pair(0);
    if (cnt > 1) issue_pair(1);

    for (int t = 0; t < cnt; t++) {
        const int pend = cnt - 1 - t;
        cpa_wait(pend);

        const bool vb = (2 * warp + 16 * t + 1) < M;

        u64 za[8], zb[8];
        const float* zs = s_ring + warp * 2048 + (t & 1) * 1024;
#pragma unroll
        for (int j = 0; j < 4; j++) {
            ulonglong2 qa = *(const ulonglong2*)(zs + j * 128 + lane * 4);
            ulonglong2 qb = *(const ulonglong2*)(zs + 512 + j * 128 + lane * 4);
            za[2*j] = qa.x; za[2*j+1] = qa.y;
            zb[2*j] = qb.x; zb[2*j+1] = qb.y;
        }
        // CORRECTNESS GATE: zero invalid row b before ANY use.
        if (!vb) {
#pragma unroll
            for (int i = 0; i < 8; i++) zb[i] = 0ull;
        }
        if (t + 2 < cnt) issue_pair(t + 2);

        // dots (cw from shared): 4 independent chains
        u64 p0a = 0ull, p1a = 0ull, p0b = 0ull, p1b = 0ull;
#pragma unroll
        for (int j = 0; j < 4; j++) {
            const int off = 4 * (j * 32 + lane);
            ulonglong2 w0 = *(const ulonglong2*)(s_cw0 + off);
            ulonglong2 w1 = *(const ulonglong2*)(s_cw1 + off);
            p0a = ffma2(w0.x, za[2*j], p0a); p0a = ffma2(w0.y, za[2*j+1], p0a);
            p1a = ffma2(w1.x, za[2*j], p1a); p1a = ffma2(w1.y, za[2*j+1], p1a);
            p0b = ffma2(w0.x, zb[2*j], p0b); p0b = ffma2(w0.y, zb[2*j+1], p0b);
            p1b = ffma2(w1.x, zb[2*j], p1b); p1b = ffma2(w1.y, zb[2*j+1], p1b);
        }
        float x, y, s0a, s1a, s0b, s1b;
        unpack2(p0a, x, y); s0a = x + y;
        unpack2(p1a, x, y); s1a = x + y;
        unpack2(p0b, x, y); s0b = x + y;
        unpack2(p1b, x, y); s1b = x + y;
#pragma unroll
        for (int o = 16; o; o >>= 1) {
            s0a += __shfl_xor_sync(0xffffffffu, s0a, o);
            s1a += __shfl_xor_sync(0xffffffffu, s1a, o);
            s0b += __shfl_xor_sync(0xffffffffu, s0b, o);
            s1b += __shfl_xor_sync(0xffffffffu, s1b, o);
        }
        const float w0a = tanh_ap(s0a), w1a = tanh_ap(s1a);
        const float w0b = tanh_ap(s0b), w1b = tanh_ap(s1b);
        const u64 w0ap = pack2(w0a, w0a), w1ap = pack2(w1a, w1a);
        const u64 w0bp = pack2(w0b, w0b), w1bp = pack2(w1b, w1b);

        // accumulate co_w*z; comment logits for both rows
        u64 lpa = 0ull, lpb = 0ull;
#pragma unroll
        for (int j = 0; j < 4; j++) {
            const int off = 4 * (j * 32 + lane);
            ulonglong2 c0v = *(const ulonglong2*)(s_c0 + off);
            ulonglong2 c1v = *(const ulonglong2*)(s_c1 + off);
            ulonglong2 wv  = *(const ulonglong2*)(s_Wco + off);
#pragma unroll
            for (int h = 0; h < 2; h++) {
                const int i = 2 * j + h;
                const u64 c0 = h ? c0v.y : c0v.x;
                const u64 c1 = h ? c1v.y : c1v.x;
                const u64 wc = h ? wv.y  : wv.x;
                acc0p[i] = ffma2(w0ap, za[i], acc0p[i]);
                acc1p[i] = ffma2(w1ap, za[i], acc1p[i]);
                u64 va = ffma2(w0ap, c0, ffma2(w1ap, c1, za[i]));
                unpack2(va, x, y);
                lpa = ffma2(pack2(tanh_ap(x), tanh_ap(y)), wc, lpa);

                acc0p[i] = ffma2(w0bp, zb[i], acc0p[i]);
                acc1p[i] = ffma2(w1bp, zb[i], acc1p[i]);
                u64 vb2 = ffma2(w0bp, c0, ffma2(w1bp, c1, zb[i]));
                unpack2(vb2, x, y);
                lpb = ffma2(pack2(tanh_ap(x), tanh_ap(y)), wc, lpb);
            }
        }
        float la, lb;
        unpack2(lpa, x, y); la = x + y;
        unpack2(lpb, x, y); lb = x + y;
#pragma unroll
        for (int o = 16; o; o >>= 1) {
            la += __shfl_xor_sync(0xffffffffu, la, o);
            lb += __shfl_xor_sync(0xffffffffu, lb, o);
        }

        // plain softmax accumulation (|l| <= ||W_co||_1 ~ 18)
        const float pa = __expf(la);
        Zrun += pa;
        const u64 ppa = pack2(pa, pa);
#pragma unroll
        for (int i = 0; i < 8; i++) aap[i] = ffma2(ppa, za[i], aap[i]);
        if (vb) {
            const float pb = __expf(lb);
            Zrun += pb;
            const u64 ppb = pack2(pb, pb);
#pragma unroll
            for (int i = 0; i < 8; i++) aap[i] = ffma2(ppb, zb[i], aap[i]);
        }
    }

    // spill per-warp partials into own ring region (2048 floats each, done with it)
    float* rw = s_ring + warp * 2048;
#pragma unroll
    for (int j = 0; j < 4; j++) {
        const int off = 4 * (j * 32 + lane);
        *(ulonglong2*)(rw + off)        = make_ulonglong2(acc0p[2*j], acc0p[2*j+1]);
        *(ulonglong2*)(rw + 512 + off)  = make_ulonglong2(acc1p[2*j], acc1p[2*j+1]);
        *(ulonglong2*)(rw + 1024 + off) = make_ulonglong2(aap[2*j],   aap[2*j+1]);
    }
    if (lane == 0) s_z[warp] = Zrun;
    __syncthreads();

    // cross-warp combine; thread t owns d = 2t, 2t+1
    const float Zg = s_z[0] + s_z[1] + s_z[2] + s_z[3]
                   + s_z[4] + s_z[5] + s_z[6] + s_z[7];
    const float invZ = 1.f / Zg;

    float a0x = 0.f, a0y = 0.f, a1x = 0.f, a1y = 0.f, avx = 0.f, avy = 0.f;
#pragma unroll
    for (int w = 0; w < 8; w++) {
        const float* rb = s_ring + w * 2048;
        float2 x0 = *(const float2*)(rb + 2*tid);
        float2 x1 = *(const float2*)(rb + 512 + 2*tid);
        float2 xa = *(const float2*)(rb + 1024 + 2*tid);
        a0x += x0.x; a0y += x0.y;
        a1x += x1.x; a1y += x1.y;
        avx += xa.x; avy += xa.y;
    }

    float2 c0v = *(const float2*)(s_c0 + 2*tid);
    float2 c1v = *(const float2*)(s_c1 + 2*tid);
    float2 wca = *(const float2*)(s_Wca + 2*tid);
    float cl0 = tanh_ap(c0v.x + a0x) * wca.x + tanh_ap(c0v.y + a0y) * wca.y;
    float cl1 = tanh_ap(c1v.x + a1x) * wca.x + tanh_ap(c1v.y + a1y) * wca.y;
#pragma unroll
    for (int o = 16; o; o >>= 1) {
        cl0 += __shfl_xor_sync(0xffffffffu, cl0, o);
        cl1 += __shfl_xor_sync(0xffffffffu, cl1, o);
    }
    if (lane == 0) { s_scalar[warp] = cl0; s_scalar[8 + warp] = cl1; }
    __syncthreads();
    cl0 = 0.f; cl1 = 0.f;
#pragma unroll
    for (int w = 0; w < 8; w++) { cl0 += s_scalar[w]; cl1 += s_scalar[8 + w]; }

    const float mx = fmaxf(cl0, cl1);
    const float e0 = __expf(cl0 - mx), e1 = __expf(cl1 - mx);
    const float einv = 1.f / (e0 + e1);
    const float wc0 = e0 * einv, wc1 = e1 * einv;

    float2 o1;
    o1.x = fmaf(c0v.x, wc0, c1v.x * wc1);
    o1.y = fmaf(c0v.y, wc0, c1v.y * wc1);
    *(float2*)(out + (size_t)b * DD + 2*tid) = o1;

    float2 o2 = make_float2(avx * invZ, avy * invZ);
    *(float2*)(out + (size_t)BB * DD + (size_t)b * DD + 2*tid) = o2;

    if (tid == 0) {
        out[(size_t)2 * BB * DD + (size_t)b * 2 + 0] = wc0;
        out[(size_t)2 * BB * DD + (size_t)b * 2 + 1] = wc1;
    }
}

#define FUSED_SMEM_BYTES ((16384 + 6 * 512 + 32) * 4)

extern "C" void kernel_launch(void* const* d_in, const int* in_sizes, int n_in,
                              void* d_out, int out_size)
{
    (void)in_sizes; (void)n_in; (void)out_size;
    const float* text        = (const float*)d_in[0];
    const float* img         = (const float*)d_in[1];
    const float* comment     = (const float*)d_in[2];
    const int*   comment_num = (const int*)d_in[3];
    const float* cow         = (const float*)d_in[4];
    const float* W_ca        = (const float*)d_in[5];
    const float* W_co        = (const float*)d_in[7];
    float* out = (float*)d_out;

    static int attr_done = 0;
    if (!attr_done) {
        cudaFuncSetAttribute(fused_coattn,
                             cudaFuncAttributeMaxDynamicSharedMemorySize,
                             FUSED_SMEM_BYTES);
        attr_done = 1;
    }

    convert_inputs<<<2048 + 256, 256>>>(text, img, cow);
    dim3 gg(DD / 128, 4096 / 128);
    cw_gemm<<<gg, 256>>>();
    fused_coattn<<<BB, 256, FUSED_SMEM_BYTES>>>(text, img, comment, comment_num,
                                                W_ca, W_co, out);
}

// round 14
// speedup vs baseline: 1.0660x; 1.0660x over previous
#include <cuda_runtime.h>
#include <cuda_bf16.h>
#include <mma.h>

using namespace nvcuda;

#define BB 2048
#define NN 128
#define DD 512

typedef unsigned long long u64;

// static scratch (no allocs allowed)
__device__ float g_cw[2 * BB * DD];                    // 8 MB
__device__ __nv_bfloat16 g_Ah[2 * BB * DD];            // 4 MB  [text;img] hi
__device__ __nv_bfloat16 g_Al[2 * BB * DD];            // 4 MB  lo
__device__ __nv_bfloat16 g_Bh[DD * DD];                // 512 KB cow hi
__device__ __nv_bfloat16 g_Bl[DD * DD];                // 512 KB cow lo

__device__ __forceinline__ float tanh_ap(float x) {
    float y;
    asm("tanh.approx.f32 %0, %1;" : "=f"(y) : "f"(x));
    return y;
}
__device__ __forceinline__ u64 ffma2(u64 a, u64 b, u64 c) {
    u64 d;
    asm("fma.rn.f32x2 %0, %1, %2, %3;" : "=l"(d) : "l"(a), "l"(b), "l"(c));
    return d;
}
__device__ __forceinline__ u64 pack2(float lo, float hi) {
    u64 r;
    asm("mov.b64 %0, {%1, %2};" : "=l"(r) : "f"(lo), "f"(hi));
    return r;
}
__device__ __forceinline__ void unpack2(u64 v, float& lo, float& hi) {
    asm("mov.b64 {%0, %1}, %2;" : "=f"(lo), "=f"(hi) : "l"(v));
}
__device__ __forceinline__ void bsplit(float x, __nv_bfloat16& h, __nv_bfloat16& l) {
    __nv_bfloat16 hh = __float2bfloat16(x);
    h = hh;
    l = __float2bfloat16(x - __bfloat162float(hh));
}
__device__ __forceinline__ void cpa_wait(int pend) {
    if (pend <= 0) asm volatile("cp.async.wait_group 0;" ::: "memory");
    else           asm volatile("cp.async.wait_group 1;" ::: "memory");
}
__device__ __forceinline__ void cpa16(unsigned dst, const void* src) {
    asm volatile("cp.async.ca.shared.global [%0], [%1], 16;"
                 :: "r"(dst), "l"(src) : "memory");
}

// ---------------------------------------------------------------------------
// Kernel 0: one-shot fp32 -> bf16 hi/lo split of A=[text;img] and B=cow.
// ---------------------------------------------------------------------------
__global__ __launch_bounds__(256) void convert_inputs(
    const float* __restrict__ text, const float* __restrict__ img,
    const float* __restrict__ cow)
{
    const int bid = blockIdx.x;
    __nv_bfloat16 h[4], l[4];
    if (bid < 2048) {
        const int e = (bid * 256 + threadIdx.x) * 4;
        const int r = e >> 9, c = e & 511;
        const float* src = (r < BB) ? (text + (size_t)r * DD + c)
                                    : (img + (size_t)(r - BB) * DD + c);
        float4 v = *(const float4*)src;
        bsplit(v.x, h[0], l[0]); bsplit(v.y, h[1], l[1]);
        bsplit(v.z, h[2], l[2]); bsplit(v.w, h[3], l[3]);
        uint2 uh, ul;
        uh.x = (unsigned)__bfloat16_as_ushort(h[0]) | ((unsigned)__bfloat16_as_ushort(h[1]) << 16);
        uh.y = (unsigned)__bfloat16_as_ushort(h[2]) | ((unsigned)__bfloat16_as_ushort(h[3]) << 16);
        ul.x = (unsigned)__bfloat16_as_ushort(l[0]) | ((unsigned)__bfloat16_as_ushort(l[1]) << 16);
        ul.y = (unsigned)__bfloat16_as_ushort(l[2]) | ((unsigned)__bfloat16_as_ushort(l[3]) << 16);
        *(uint2*)&g_Ah[e] = uh;
        *(uint2*)&g_Al[e] = ul;
    } else {
        const int e = ((bid - 2048) * 256 + threadIdx.x) * 4;
        float4 v = *(const float4*)(cow + e);
        bsplit(v.x, h[0], l[0]); bsplit(v.y, h[1], l[1]);
        bsplit(v.z, h[2], l[2]); bsplit(v.w, h[3], l[3]);
        uint2 uh, ul;
        uh.x = (unsigned)__bfloat16_as_ushort(h[0]) | ((unsigned)__bfloat16_as_ushort(h[1]) << 16);
        uh.y = (unsigned)__bfloat16_as_ushort(h[2]) | ((unsigned)__bfloat16_as_ushort(h[3]) << 16);
        ul.x = (unsigned)__bfloat16_as_ushort(l[0]) | ((unsigned)__bfloat16_as_ushort(l[1]) << 16);
        ul.y = (unsigned)__bfloat16_as_ushort(l[2]) | ((unsigned)__bfloat16_as_ushort(l[3]) << 16);
        *(uint2*)&g_Bh[e] = uh;
        *(uint2*)&g_Bl[e] = ul;
    }
}

// ---------------------------------------------------------------------------
// Kernel A: cw = A @ cow, bf16 hi/lo split (3 MMAs), cp.async 3-stage ring.
// 128x128 tile, K-chunk 32, 256 threads, 1 sync per chunk. grid = (4, 32).
// Stage layout (bf16 elems): Ah[128*40]=5120, Al=5120, Bh[32*136]=4352, Bl=4352.
// ---------------------------------------------------------------------------
#define GA_H 0
#define GA_L 5120
#define GB_H 10240
#define GB_L 14592
#define GSTAGE 18944
#define GEMM_SMEM_BYTES (3 * GSTAGE * 2)

__global__ __launch_bounds__(256, 1) void cw_gemm()
{
    extern __shared__ __nv_bfloat16 sm[];
    const int rowBase = blockIdx.y * 128;
    const int colBase = blockIdx.x * 128;
    const int tid = threadIdx.x;
    const int warp = tid >> 5;
    const int wm = warp >> 2;
    const int wn = warp & 3;

    const unsigned smem_base = (unsigned)__cvta_generic_to_shared(sm);

    auto issue = [&](int it, int s) {
        const int kc = it * 32;
        const unsigned sb = smem_base + (unsigned)(s * GSTAGE) * 2u;
#pragma unroll
        for (int u = 0; u < 2; u++) {
            const int idx = tid + u * 256;           // 0..511
            const int r = idx >> 2, c = idx & 3;     // A: 128 rows x 4 chunks
            const unsigned dA = sb + (unsigned)(r * 40 + c * 8) * 2u;
            const size_t gA = (size_t)(rowBase + r) * DD + kc + c * 8;
            cpa16(dA, &g_Ah[gA]);
            cpa16(dA + (unsigned)(GA_L) * 2u, &g_Al[gA]);
        }
#pragma unroll
        for (int u = 0; u < 2; u++) {
            const int idx = tid + u * 256;
            const int r = idx >> 4, c = idx & 15;    // B: 32 rows x 16 chunks
            const unsigned dB = sb + (unsigned)(GB_H + r * 136 + c * 8) * 2u;
            const size_t gB = (size_t)(kc + r) * DD + colBase + c * 8;
            cpa16(dB, &g_Bh[gB]);
            cpa16(dB + (unsigned)(GB_L - GB_H) * 2u, &g_Bl[gB]);
        }
        asm volatile("cp.async.commit_group;" ::: "memory");
    };

    wmma::fragment<wmma::accumulator, 16, 16, 16, float> acc[4][2];
#pragma unroll
    for (int i = 0; i < 4; i++)
#pragma unroll
        for (int j = 0; j < 2; j++) wmma::fill_fragment(acc[i][j], 0.0f);

    auto compute = [&](int s) {
        const __nv_bfloat16* Ah = sm + s * GSTAGE;
        const __nv_bfloat16* Al = Ah + GA_L;
        const __nv_bfloat16* Bh = Ah + GB_H;
        const __nv_bfloat16* Bl = Ah + GB_L;
#pragma unroll
        for (int ks = 0; ks < 32; ks += 16) {
            wmma::fragment<wmma::matrix_a, 16, 16, 16, __nv_bfloat16, wmma::row_major> ah[4], al[4];
            wmma::fragment<wmma::matrix_b, 16, 16, 16, __nv_bfloat16, wmma::row_major> bh[2], bl[2];
#pragma unroll
            for (int i = 0; i < 4; i++) {
                wmma::load_matrix_sync(ah[i], Ah + (wm*64 + i*16) * 40 + ks, 40);
                wmma::load_matrix_sync(al[i], Al + (wm*64 + i*16) * 40 + ks, 40);
            }
#pragma unroll
            for (int j = 0; j < 2; j++) {
                wmma::load_matrix_sync(bh[j], Bh + ks * 136 + wn*32 + j*16, 136);
                wmma::load_matrix_sync(bl[j], Bl + ks * 136 + wn*32 + j*16, 136);
            }
#pragma unroll
            for (int i = 0; i < 4; i++)
#pragma unroll
                for (int j = 0; j < 2; j++) {
                    wmma::mma_sync(acc[i][j], ah[i], bh[j], acc[i][j]);
                    wmma::mma_sync(acc[i][j], ah[i], bl[j], acc[i][j]);
                    wmma::mma_sync(acc[i][j], al[i], bh[j], acc[i][j]);
                }
        }
    };

    issue(0, 0);
    issue(1, 1);
    for (int it = 0; it < 16; it++) {
        if (it + 1 < 16) asm volatile("cp.async.wait_group 1;" ::: "memory");
        else             asm volatile("cp.async.wait_group 0;" ::: "memory");
        __syncthreads();
        compute(it % 3);
        if (it + 2 < 16) issue(it + 2, (it + 2) % 3);
    }

    float* C = g_cw + (size_t)rowBase * DD;
#pragma unroll
    for (int i = 0; i < 4; i++)
#pragma unroll
        for (int j = 0; j < 2; j++)
            wmma::store_matrix_sync(
                C + (size_t)(wm*64 + i*16) * DD + colBase + wn*32 + j*16,
                acc[i][j], DD, wmma::mem_row_major);
}

// ---------------------------------------------------------------------------
// Kernel B: fused co-attention (R12 config — proven fastest). One CTA/sample,
// 4 warps, row PAIRS per iter, 2-stage x 2-row cp.async ring (static smem).
// Invalid row b zeroed in regs before any use.
// ---------------------------------------------------------------------------
__global__ __launch_bounds__(128, 3) void fused_coattn(
    const float* __restrict__ text, const float* __restrict__ img,
    const float* __restrict__ comment, const int* __restrict__ comment_num,
    const float* __restrict__ W_ca, const float* __restrict__ W_co,
    float* __restrict__ out)
{
    const int b = blockIdx.x;
    const int tid = threadIdx.x;
    const int lane = tid & 31;
    const int warp = tid >> 5;
    const int M = comment_num[b];
    const float* __restrict__ comment_b = comment + (size_t)b * NN * DD;

    __shared__ float s_ring[4][2][2][512];  // 32 KB; aliased as reduce scratch later
    __shared__ float s_c0[DD], s_c1[DD], s_Wca[DD], s_Wco[DD];
    __shared__ float s_z[4];
    __shared__ float s_scalar[8];

    for (int i = tid; i < DD / 4; i += 128) {
        ((float4*)s_c0)[i]  = ((const float4*)(text + (size_t)b * DD))[i];
        ((float4*)s_c1)[i]  = ((const float4*)(img  + (size_t)b * DD))[i];
        ((float4*)s_Wca)[i] = ((const float4*)W_ca)[i];
        ((float4*)s_Wco)[i] = ((const float4*)W_co)[i];
    }
    __syncthreads();

    // packed cw register vectors (d = 4*(j*32+lane)+c)
    u64 cw0p[8], cw1p[8];
    {
        const float* cw0g = g_cw + (size_t)b * DD;
        const float* cw1g = g_cw + (size_t)BB * DD + (size_t)b * DD;
#pragma unroll
        for (int j = 0; j < 4; j++) {
            const int off = 4 * (j * 32 + lane);
            ulonglong2 t0 = *(const ulonglong2*)(cw0g + off);
            ulonglong2 t1 = *(const ulonglong2*)(cw1g + off);
            cw0p[2*j] = t0.x; cw0p[2*j+1] = t0.y;
            cw1p[2*j] = t1.x; cw1p[2*j+1] = t1.y;
        }
    }

    u64 acc0p[8], acc1p[8], aap[8];
#pragma unroll
    for (int i = 0; i < 8; i++) { acc0p[i] = 0ull; acc1p[i] = 0ull; aap[i] = 0ull; }
    float Zrun = 0.f;

    const int cnt = (M > 2 * warp) ? ((M - 2 * warp + 7) >> 3) : 0;
    const unsigned ring_addr =
        (unsigned)__cvta_generic_to_shared(&s_ring[warp][0][0][0]);

    auto issue_pair = [&](int t) {
        const int r0 = 2 * warp + 8 * t;
        const int r1 = (r0 + 1 < NN) ? r0 + 1 : r0;   // clamp; invalid row zeroed in regs
        const float* g0 = comment_b + (size_t)r0 * DD + lane * 4;
        const float* g1 = comment_b + (size_t)r1 * DD + lane * 4;
        const unsigned s = ring_addr + ((unsigned)(t & 1) << 12) + ((unsigned)lane << 4);
#pragma unroll
        for (int j = 0; j < 4; j++)
            asm volatile("cp.async.cg.shared.global [%0], [%1], 16;"
                         :: "r"(s + j * 512), "l"(g0 + j * 128) : "memory");
#pragma unroll
        for (int j = 0; j < 4; j++)
            asm volatile("cp.async.cg.shared.global [%0], [%1], 16;"
                         :: "r"(s + 2048 + j * 512), "l"(g1 + j * 128) : "memory");
        asm volatile("cp.async.commit_group;" ::: "memory");
    };

    if (cnt > 0) issue_pair(0);
    if (cnt > 1) issue_pair(1);

    for (int t = 0; t < cnt; t++) {
        const int pend = cnt - 1 - t;
        cpa_wait(pend);

        const bool vb = (2 * warp + 8 * t + 1) < M;

        u64 za[8], zb[8];
        const float* zs = &s_ring[warp][t & 1][0][0];
#pragma unroll
        for (int j = 0; j < 4; j++) {
            ulonglong2 qa = *(const ulonglong2*)(zs + j * 128 + lane * 4);
            ulonglong2 qb = *(const ulonglong2*)(zs + 512 + j * 128 + lane * 4);
            za[2*j] = qa.x; za[2*j+1] = qa.y;
            zb[2*j] = qb.x; zb[2*j+1] = qb.y;
        }
        // CORRECTNESS GATE: zero invalid row b before ANY use.
        if (!vb) {
#pragma unroll
            for (int i = 0; i < 8; i++) zb[i] = 0ull;
        }
        if (t + 2 < cnt) issue_pair(t + 2);

        // dots: 4 independent chains
        u64 p0a = 0ull, p1a = 0ull, p0b = 0ull, p1b = 0ull;
#pragma unroll
        for (int i = 0; i < 8; i++) {
            p0a = ffma2(cw0p[i], za[i], p0a);
            p1a = ffma2(cw1p[i], za[i], p1a);
            p0b = ffma2(cw0p[i], zb[i], p0b);
            p1b = ffma2(cw1p[i], zb[i], p1b);
        }
        float x, y, s0a, s1a, s0b, s1b;
        unpack2(p0a, x, y); s0a = x + y;
        unpack2(p1a, x, y); s1a = x + y;
        unpack2(p0b, x, y); s0b = x + y;
        unpack2(p1b, x, y); s1b = x + y;
#pragma unroll
        for (int o = 16; o; o >>= 1) {
            s0a += __shfl_xor_sync(0xffffffffu, s0a, o);
            s1a += __shfl_xor_sync(0xffffffffu, s1a, o);
            s0b += __shfl_xor_sync(0xffffffffu, s0b, o);
            s1b += __shfl_xor_sync(0xffffffffu, s1b, o);
        }
        const float w0a = tanh_ap(s0a), w1a = tanh_ap(s1a);
        const float w0b = tanh_ap(s0b), w1b = tanh_ap(s1b);
        const u64 w0ap = pack2(w0a, w0a), w1ap = pack2(w1a, w1a);
        const u64 w0bp = pack2(w0b, w0b), w1bp = pack2(w1b, w1b);

        // accumulate co_w*z; comment logits for both rows
        u64 lpa = 0ull, lpb = 0ull;
#pragma unroll
        for (int j = 0; j < 4; j++) {
            const int off = 4 * (j * 32 + lane);
            ulonglong2 c0v = *(const ulonglong2*)(s_c0 + off);
            ulonglong2 c1v = *(const ulonglong2*)(s_c1 + off);
            ulonglong2 wv  = *(const ulonglong2*)(s_Wco + off);
#pragma unroll
            for (int h = 0; h < 2; h++) {
                const int i = 2 * j + h;
                const u64 c0 = h ? c0v.y : c0v.x;
                const u64 c1 = h ? c1v.y : c1v.x;
                const u64 wc = h ? wv.y  : wv.x;
                acc0p[i] = ffma2(w0ap, za[i], acc0p[i]);
                acc1p[i] = ffma2(w1ap, za[i], acc1p[i]);
                u64 va = ffma2(w0ap, c0, ffma2(w1ap, c1, za[i]));
                unpack2(va, x, y);
                lpa = ffma2(pack2(tanh_ap(x), tanh_ap(y)), wc, lpa);

                acc0p[i] = ffma2(w0bp, zb[i], acc0p[i]);
                acc1p[i] = ffma2(w1bp, zb[i], acc1p[i]);
                u64 vb2 = ffma2(w0bp, c0, ffma2(w1bp, c1, zb[i]));
                unpack2(vb2, x, y);
                lpb = ffma2(pack2(tanh_ap(x), tanh_ap(y)), wc, lpb);
            }
        }
        float la, lb;
        unpack2(lpa, x, y); la = x + y;
        unpack2(lpb, x, y); lb = x + y;
#pragma unroll
        for (int o = 16; o; o >>= 1) {
            la += __shfl_xor_sync(0xffffffffu, la, o);
            lb += __shfl_xor_sync(0xffffffffu, lb, o);
        }

        // plain softmax accumulation (|l| <= ||W_co||_1 ~ 18)
        const float pa = __expf(la);
        Zrun += pa;
        const u64 ppa = pack2(pa, pa);
#pragma unroll
        for (int i = 0; i < 8; i++) aap[i] = ffma2(ppa, za[i], aap[i]);
        if (vb) {
            const float pb = __expf(lb);
            Zrun += pb;
            const u64 ppb = pack2(pb, pb);
#pragma unroll
            for (int i = 0; i < 8; i++) aap[i] = ffma2(ppb, zb[i], aap[i]);
        }
    }

    // spill per-warp partials into own ring region
    float* rw = &s_ring[warp][0][0][0];
#pragma unroll
    for (int j = 0; j < 4; j++) {
        const int off = 4 * (j * 32 + lane);
        *(ulonglong2*)(rw + off)        = make_ulonglong2(acc0p[2*j], acc0p[2*j+1]);
        *(ulonglong2*)(rw + 512 + off)  = make_ulonglong2(acc1p[2*j], acc1p[2*j+1]);
        *(ulonglong2*)(rw + 1024 + off) = make_ulonglong2(aap[2*j],   aap[2*j+1]);
    }
    if (lane == 0) s_z[warp] = Zrun;
    __syncthreads();

    const float Zg = s_z[0] + s_z[1] + s_z[2] + s_z[3];
    const float invZ = 1.f / Zg;

    float a0[4] = {0,0,0,0}, a1[4] = {0,0,0,0}, av[4] = {0,0,0,0};
#pragma unroll
    for (int w = 0; w < 4; w++) {
        const float* rb = &s_ring[w][0][0][0];
        float4 x0 = *(const float4*)(rb + 4*tid);
        float4 x1 = *(const float4*)(rb + 512 + 4*tid);
        float4 xa = *(const float4*)(rb + 1024 + 4*tid);
        a0[0]+=x0.x; a0[1]+=x0.y; a0[2]+=x0.z; a0[3]+=x0.w;
        a1[0]+=x1.x; a1[1]+=x1.y; a1[2]+=x1.z; a1[3]+=x1.w;
        av[0]+=xa.x; av[1]+=xa.y; av[2]+=xa.z; av[3]+=xa.w;
    }

    float4 c0v = *(const float4*)(s_c0 + 4*tid);
    float4 c1v = *(const float4*)(s_c1 + 4*tid);
    float4 wca = *(const float4*)(s_Wca + 4*tid);
    float cl0 = tanh_ap(c0v.x + a0[0]) * wca.x + tanh_ap(c0v.y + a0[1]) * wca.y
              + tanh_ap(c0v.z + a0[2]) * wca.z + tanh_ap(c0v.w + a0[3]) * wca.w;
    float cl1 = tanh_ap(c1v.x + a1[0]) * wca.x + tanh_ap(c1v.y + a1[1]) * wca.y
              + tanh_ap(c1v.z + a1[2]) * wca.z + tanh_ap(c1v.w + a1[3]) * wca.w;
#pragma unroll
    for (int o = 16; o; o >>= 1) {
        cl0 += __shfl_xor_sync(0xffffffffu, cl0, o);
        cl1 += __shfl_xor_sync(0xffffffffu, cl1, o);
    }
    if (lane == 0) { s_scalar[warp] = cl0; s_scalar[4 + warp] = cl1; }
    __syncthreads();
    cl0 = s_scalar[0] + s_scalar[1] + s_scalar[2] + s_scalar[3];
    cl1 = s_scalar[4] + s_scalar[5] + s_scalar[6] + s_scalar[7];

    const float mx = fmaxf(cl0, cl1);
    const float e0 = __expf(cl0 - mx), e1 = __expf(cl1 - mx);
    const float einv = 1.f / (e0 + e1);
    const float wc0 = e0 * einv, wc1 = e1 * einv;

    float4 o1;
    o1.x = fmaf(c0v.x, wc0, c1v.x * wc1);
    o1.y = fmaf(c0v.y, wc0, c1v.y * wc1);
    o1.z = fmaf(c0v.z, wc0, c1v.z * wc1);
    o1.w = fmaf(c0v.w, wc0, c1v.w * wc1);
    *(float4*)(out + (size_t)b * DD + 4*tid) = o1;

    float4 o2 = make_float4(av[0]*invZ, av[1]*invZ, av[2]*invZ, av[3]*invZ);
    *(float4*)(out + (size_t)BB * DD + (size_t)b * DD + 4*tid) = o2;

    if (tid == 0) {
        out[(size_t)2 * BB * DD + (size_t)b * 2 + 0] = wc0;
        out[(size_t)2 * BB * DD + (size_t)b * 2 + 1] = wc1;
    }
}

extern "C" void kernel_launch(void* const* d_in, const int* in_sizes, int n_in,
                              void* d_out, int out_size)
{
    (void)in_sizes; (void)n_in; (void)out_size;
    const float* text        = (const float*)d_in[0];
    const float* img         = (const float*)d_in[1];
    const float* comment     = (const float*)d_in[2];
    const int*   comment_num = (const int*)d_in[3];
    const float* cow         = (const float*)d_in[4];
    const float* W_ca        = (const float*)d_in[5];
    const float* W_co        = (const float*)d_in[7];
    float* out = (float*)d_out;

    static int attr_done = 0;
    if (!attr_done) {
        cudaFuncSetAttribute(cw_gemm,
                             cudaFuncAttributeMaxDynamicSharedMemorySize,
                             GEMM_SMEM_BYTES);
        attr_done = 1;
    }

    convert_inputs<<<2048 + 256, 256>>>(text, img, cow);
    dim3 gg(DD / 128, 4096 / 128);
    cw_gemm<<<gg, 256, GEMM_SMEM_BYTES>>>();
    fused_coattn<<<BB, 128>>>(text, img, comment, comment_num, W_ca, W_co, out);
}